// round 7
// baseline (speedup 1.0000x reference)
#include <cuda_runtime.h>

// Problem constants
#define NG 2048   // G
#define NC 16     // C
#define NM 16     // m
// exp(x/gamma) = ex2(x * 100 * log2(e));  gamma*ln(s) = lg2(s) * gamma*ln2
#define KEXP 144.2695040889f
#define KLOG 0.00693147180560f

#define NBLK 592                 // 148 SMs * 4 blocks; launch_bounds(256,4)
#define NTHR 256
#define NW   (NBLK * 8)          // 4736 warps
#define NPAIR (NC * NG / 2)      // 16384 item-pairs in Phase A

typedef unsigned long long u64;

// Packed layouts: element [g*16+j] = (val[b=2j], val[b=2j+1])
// g_R: 6 single-use buffers -> no SM ever reads a line it cached pre-write,
// so plain L1-cached loads are safe with flush-free barriers.
__device__ u64   g_R[6][NG * 16];
__device__ u64   g_Cv2[NC * NG * 16];    // written Phase A, read Phase B via ld.cg
__device__ float g_Ws[NM * NC];          // read via ld.cg once
__device__ int   g_max[16][8];           // banked float-bit maxes; read via ld.cg
// slot 3i=Cv max, 3i+1=Hs max, 3i+2=R max (iter i); slot 15 = constant 1.0
__device__ unsigned g_cnt;               // barrier arrivals (self-resetting)
__device__ unsigned g_gen;               // barrier generation (monotonic, NEVER reset)

// ---- f32x2 helpers (sm_103a packed fp32) ----
__device__ __forceinline__ u64 pk(float x, float y) {
    u64 v; asm("mov.b64 %0, {%1,%2};" : "=l"(v) : "f"(x), "f"(y)); return v;
}
__device__ __forceinline__ float2 unpk(u64 v) {
    float2 r; asm("mov.b64 {%0,%1}, %2;" : "=f"(r.x), "=f"(r.y) : "l"(v)); return r;
}
__device__ __forceinline__ u64 mul2(u64 a, u64 b) {
    u64 c; asm("mul.rn.f32x2 %0, %1, %2;" : "=l"(c) : "l"(a), "l"(b)); return c;
}
__device__ __forceinline__ u64 fma2(u64 a, u64 b, u64 c) {
    u64 d; asm("fma.rn.f32x2 %0, %1, %2, %3;" : "=l"(d) : "l"(a), "l"(b), "l"(c)); return d;
}
__device__ __forceinline__ float ex2(float x) {
    float y; asm("ex2.approx.ftz.f32 %0, %1;" : "=f"(y) : "f"(x)); return y;
}
__device__ __forceinline__ float lg2(float x) {
    float y; asm("lg2.approx.f32 %0, %1;" : "=f"(y) : "f"(x)); return y;
}
// ---- L2-direct loads (bypass possibly-stale L1) ----
__device__ __forceinline__ int ldcg(const int* p) {
    int v; asm volatile("ld.global.cg.b32 %0, [%1];" : "=r"(v) : "l"(p)); return v;
}
__device__ __forceinline__ u64 ldcg64(const u64* p) {
    u64 v; asm volatile("ld.global.cg.b64 %0, [%1];" : "=l"(v) : "l"(p)); return v;
}
__device__ __forceinline__ float ldcgf(const float* p) {
    float v; asm volatile("ld.global.cg.f32 %0, [%1];" : "=f"(v) : "l"(p)); return v;
}

// ---------------------------------------------------------------------------
__device__ __forceinline__ float get_scale(int slot) {
    int v = ldcg(&g_max[slot][0]);
    #pragma unroll
    for (int k = 1; k < 8; k++) v = max(v, ldcg(&g_max[slot][k]));
    float m = __int_as_float(v);
    return (m > 1.0f) ? __fdividef(1.0f, m) : 1.0f;
}

__device__ __forceinline__ void block_max_atomic(float val, int slot) {
    int v = __float_as_int(val);   // valid ordering: all values non-negative
    #pragma unroll
    for (int o = 16; o > 0; o >>= 1) v = max(v, __shfl_xor_sync(0xffffffffu, v, o));
    __shared__ int s_red[8];
    if ((threadIdx.x & 31) == 0) s_red[threadIdx.x >> 5] = v;
    __syncthreads();
    if (threadIdx.x == 0) {
        int m = s_red[0];
        #pragma unroll
        for (int k = 1; k < 8; k++) m = max(m, s_red[k]);
        atomicMax(&g_max[slot][blockIdx.x & 7], m);
    }
}

// Flush-free grid barrier: scoped acq/rel through L2, NO CCTL.IVALL.
__device__ __forceinline__ void gsync() {
    __syncthreads();
    if (threadIdx.x == 0) {
        unsigned gen;
        asm volatile("ld.acquire.gpu.global.b32 %0, [%1];" : "=r"(gen) : "l"(&g_gen));
        unsigned old;
        asm volatile("atom.acq_rel.gpu.global.add.u32 %0, [%1], 1;"
                     : "=r"(old) : "l"(&g_cnt) : "memory");
        if (old == NBLK - 1) {
            asm volatile("st.relaxed.gpu.global.b32 [%0], 0;" :: "l"(&g_cnt) : "memory");
            asm volatile("st.release.gpu.global.b32 [%0], %1;"
                         :: "l"(&g_gen), "r"(gen + 1) : "memory");
        } else {
            unsigned cur;
            do {
                asm volatile("ld.acquire.gpu.global.b32 %0, [%1];" : "=r"(cur) : "l"(&g_gen));
            } while (cur == gen);
        }
    }
    __syncthreads();
}

// ---------------------------------------------------------------------------
__global__ void __launch_bounds__(NTHR, 4)
k_persist(const float* __restrict__ x, const float* __restrict__ W,
          const int* __restrict__ I, float* __restrict__ out) {
    const int tid  = threadIdx.x;
    const int lane = tid & 31;
    const int hf   = lane >> 4;                   // item-of-pair selector
    const int j    = lane & 15;                   // b-pair index
    const int wid  = blockIdx.x * 8 + (tid >> 5); // 0..NW-1
    const int gtid = blockIdx.x * NTHR + tid;

    // Phase B/merge ownership: spread over ALL blocks (every 4th warp busy)
    const bool bOwn = ((wid & 3) == 0) && ((wid >> 2) < NG / 2);
    const int  g    = 2 * (wid >> 2) + hf;        // valid when bOwn

    // ---- init: pack x -> g_R[0], Ws = softmax(W), reset max banks ----
    {
        if (gtid < NG * 16) {                     // gtid = jj*NG + gg
            int jj = gtid >> 11, gg = gtid & (NG - 1);
            g_R[0][gg * 16 + jj] = pk(x[(2 * jj) * NG + gg], x[(2 * jj + 1) * NG + gg]);
        }
        if (blockIdx.x == 0 && tid < NM) {
            float mx = -1e30f;
            #pragma unroll
            for (int c = 0; c < NC; c++) mx = fmaxf(mx, W[tid * NC + c]);
            float e[NC]; float sum = 0.0f;
            #pragma unroll
            for (int c = 0; c < NC; c++) { e[c] = ex2((W[tid * NC + c] - mx) * 1.4426950409f); sum += e[c]; }
            float inv = __fdividef(1.0f, sum);
            #pragma unroll
            for (int c = 0; c < NC; c++) g_Ws[tid * NC + c] = e[c] * inv;
        }
        if (blockIdx.x == 1 && tid < 128)
            ((int*)g_max)[tid] = (tid >= 15 * 8) ? __float_as_int(1.0f) : 0;
    }
    gsync();

    __shared__ u64 ws2[NM * NC];                  // broadcast-packed softmax(W)
    { float w = ldcgf(&g_Ws[tid]); ws2[tid] = pk(w, w); }
    __syncthreads();

    int slotR = 15;   // iteration 0 uses x unscaled (slot 15 == 1.0)

    #pragma unroll 1
    for (int it = 0; it < 5; it++) {
        const int slotCv = 3 * it, slotHs = 3 * it + 1, slotRn = 3 * it + 2;
        const u64* Rin  = g_R[it];
        u64*       Rout = g_R[it + 1];

        // ---- Phase A: pair of (c,g) items per warp; f32x2; L1-cached gathers ----
        {
            float sR = get_scale(slotR);
            float s3 = sR * sR * sR;
            float kexp = s3 * KEXP;               // scale folded into LSE constant
            u64  kexp2 = pk(kexp, kexp);
            float lmax = 0.0f;
            int p0 = (int)(((long long)wid * NPAIR) / NW);
            int p1 = (int)(((long long)(wid + 1) * NPAIR) / NW);
            #pragma unroll 1
            for (int P = p0; P < p1; P++) {
                int item = 2 * P + hf;
                const int4* ip = reinterpret_cast<const int4*>(I) + item * 6;
                int4 a0 = ip[0], a1 = ip[1], a2 = ip[2],
                     a3 = ip[3], a4 = ip[4], a5 = ip[5];
                #define GA(i) Rin[(i) * 16 + j]
                u64 b0 = mul2(mul2(GA(a0.x), GA(a0.y)), GA(a0.z));
                u64 b1 = mul2(mul2(GA(a0.w), GA(a1.x)), GA(a1.y));
                u64 b2 = mul2(mul2(GA(a1.z), GA(a1.w)), GA(a2.x));
                u64 b3 = mul2(mul2(GA(a2.y), GA(a2.z)), GA(a2.w));
                u64 b4 = mul2(mul2(GA(a3.x), GA(a3.y)), GA(a3.z));
                u64 b5 = mul2(mul2(GA(a3.w), GA(a4.x)), GA(a4.y));
                u64 b6 = mul2(mul2(GA(a4.z), GA(a4.w)), GA(a5.x));
                u64 b7 = mul2(mul2(GA(a5.y), GA(a5.z)), GA(a5.w));
                #undef GA
                float2 c0 = unpk(b0), c1 = unpk(b1), c2 = unpk(b2), c3 = unpk(b3);
                float2 c4 = unpk(b4), c5 = unpk(b5), c6 = unpk(b6), c7 = unpk(b7);
                float mxx = fmaxf(fmaxf(fmaxf(c0.x, c1.x), fmaxf(c2.x, c3.x)),
                                  fmaxf(fmaxf(c4.x, c5.x), fmaxf(c6.x, c7.x)));
                float mxy = fmaxf(fmaxf(fmaxf(c0.y, c1.y), fmaxf(c2.y, c3.y)),
                                  fmaxf(fmaxf(c4.y, c5.y), fmaxf(c6.y, c7.y)));
                u64 mneg = pk(-mxx * kexp, -mxy * kexp);
                float sx = 0.0f, sy = 0.0f;
                {
                    u64 t0 = fma2(b0, kexp2, mneg); float2 f0 = unpk(t0); sx += ex2(f0.x); sy += ex2(f0.y);
                    u64 t1 = fma2(b1, kexp2, mneg); float2 f1 = unpk(t1); sx += ex2(f1.x); sy += ex2(f1.y);
                    u64 t2 = fma2(b2, kexp2, mneg); float2 f2 = unpk(t2); sx += ex2(f2.x); sy += ex2(f2.y);
                    u64 t3 = fma2(b3, kexp2, mneg); float2 f3 = unpk(t3); sx += ex2(f3.x); sy += ex2(f3.y);
                    u64 t4 = fma2(b4, kexp2, mneg); float2 f4 = unpk(t4); sx += ex2(f4.x); sy += ex2(f4.y);
                    u64 t5 = fma2(b5, kexp2, mneg); float2 f5 = unpk(t5); sx += ex2(f5.x); sy += ex2(f5.y);
                    u64 t6 = fma2(b6, kexp2, mneg); float2 f6 = unpk(t6); sx += ex2(f6.x); sy += ex2(f6.y);
                    u64 t7 = fma2(b7, kexp2, mneg); float2 f7 = unpk(t7); sx += ex2(f7.x); sy += ex2(f7.y);
                }
                float cvx = fmaf(lg2(sx), KLOG, mxx * s3);
                float cvy = fmaf(lg2(sy), KLOG, mxy * s3);
                g_Cv2[item * 16 + j] = pk(cvx, cvy);
                lmax = fmaxf(lmax, fmaxf(cvx, cvy));
            }
            block_max_atomic(lmax, slotCv);
        }
        gsync();

        // ---- Phase B: matvec + LSE_m; Cv via ld.cg; hs held in registers ----
        float hsx = 0.0f, hsy = 0.0f;
        {
            float s1 = get_scale(slotCv);
            float lmax = 0.0f;
            if (bOwn) {
                u64 h[NM];
                #pragma unroll
                for (int m = 0; m < NM; m++) h[m] = 0ull;
                #pragma unroll
                for (int c = 0; c < NC; c++) {
                    u64 cvc = ldcg64(&g_Cv2[(c * NG + g) * 16 + j]);
                    #pragma unroll
                    for (int m = 0; m < NM; m++) h[m] = fma2(ws2[m * NC + c], cvc, h[m]);
                }
                float2 hh[NM];
                #pragma unroll
                for (int m = 0; m < NM; m++) hh[m] = unpk(h[m]);
                float mxx = hh[0].x, mxy = hh[0].y;
                #pragma unroll
                for (int m = 1; m < NM; m++) { mxx = fmaxf(mxx, hh[m].x); mxy = fmaxf(mxy, hh[m].y); }
                float k1 = s1 * KEXP;
                u64 k12 = pk(k1, k1), mneg = pk(-mxx * k1, -mxy * k1);
                float sx = 0.0f, sy = 0.0f;
                #pragma unroll
                for (int m = 0; m < NM; m++) {
                    u64 t = fma2(h[m], k12, mneg);
                    float2 f = unpk(t);
                    sx += ex2(f.x); sy += ex2(f.y);
                }
                hsx = fmaf(lg2(sx), KLOG, mxx * s1);
                hsy = fmaf(lg2(sy), KLOG, mxy * s1);
                lmax = fmaxf(hsx, hsy);
            }
            block_max_atomic(lmax, slotHs);
        }
        gsync();

        // ---- merge: same warps, hs from registers; write next R buffer ----
        {
            float sR = get_scale(slotR);
            float s2 = get_scale(slotHs);
            float lmax = 0.0f;
            if (bOwn) {
                float2 rr = unpk(Rin[g * 16 + j]);
                float ax = rr.x * sR, ay = rr.y * sR;
                float bx = hsx * s2,  by = hsy * s2;
                float mxx = fmaxf(ax, bx), mnx = fminf(ax, bx);
                float mxy = fmaxf(ay, by), mny = fminf(ay, by);
                float rx = fmaf(lg2(1.0f + ex2((mnx - mxx) * KEXP)), KLOG, mxx);
                float ry = fmaf(lg2(1.0f + ex2((mny - mxy) * KEXP)), KLOG, mxy);
                Rout[g * 16 + j] = pk(rx, ry);
                lmax = fmaxf(rx, ry);
            }
            block_max_atomic(lmax, slotRn);
        }
        gsync();

        slotR = slotRn;
    }

    // ---- output: scale + unpack back to (B, G); g_R[5] untouched before ----
    if (gtid < NG * 32) {                         // gtid = b*NG + gg
        float s = get_scale(slotR);
        int b = gtid >> 11, gg = gtid & (NG - 1);
        float2 v = unpk(g_R[5][gg * 16 + (b >> 1)]);
        out[gtid] = ((b & 1) ? v.y : v.x) * s;
    }
}

// ---------------------------------------------------------------------------
extern "C" void kernel_launch(void* const* d_in, const int* in_sizes, int n_in,
                              void* d_out, int out_size) {
    const float* x = (const float*)d_in[0];   // (32, 2048) f32
    const float* W = (const float*)d_in[1];   // (16, 16) f32
    const int*   I = (const int*)  d_in[2];   // (16, 2048, 8, 3) i32
    float* out = (float*)d_out;               // (32, 2048) f32

    k_persist<<<NBLK, NTHR>>>(x, W, I, out);
}

// round 8
// speedup vs baseline: 1.0525x; 1.0525x over previous
#include <cuda_runtime.h>

// Problem constants
#define NG 2048   // G
#define NC 16     // C
#define NM 16     // m
// exp(x/gamma) = ex2(x * 100 * log2(e));  gamma*ln(s) = lg2(s) * gamma*ln2
#define KEXP 144.2695040889f
#define KLOG 0.00693147180560f

#define NBLK 592                 // 148 SMs * 4 blocks; launch_bounds(256,4)
#define NTHR 256
#define NW   (NBLK * 8)          // 4736 warps
#define NPAIR (NC * NG / 2)      // 16384 item-pairs in Phase A

typedef unsigned long long u64;

// Packed layouts: element [g*16+j] = (val[b=2j], val[b=2j+1])
// g_R: 6 single-use buffers -> no SM ever reads a line it cached pre-write,
// so plain L1-cached loads are safe with flush-free, acquire-free barriers.
__device__ u64   g_R[6][NG * 16];
__device__ u64   g_Cv2[NC * NG * 16];    // written Phase A, read Phase B via ld.cg
__device__ float g_Ws[NM * NC];          // read via ld.cg once
__device__ int   g_max[16][8];           // banked float-bit maxes; read via ld.cg
// slot 3i=Cv max, 3i+1=Hs max, 3i+2=R max (iter i); slot 15 = constant 1.0
__device__ unsigned g_cnt;               // barrier arrivals (self-resetting)
__device__ unsigned g_gen;               // barrier generation (monotonic, NEVER reset)

// ---- f32x2 helpers (sm_103a packed fp32) ----
__device__ __forceinline__ u64 pk(float x, float y) {
    u64 v; asm("mov.b64 %0, {%1,%2};" : "=l"(v) : "f"(x), "f"(y)); return v;
}
__device__ __forceinline__ float2 unpk(u64 v) {
    float2 r; asm("mov.b64 {%0,%1}, %2;" : "=f"(r.x), "=f"(r.y) : "l"(v)); return r;
}
__device__ __forceinline__ u64 mul2(u64 a, u64 b) {
    u64 c; asm("mul.rn.f32x2 %0, %1, %2;" : "=l"(c) : "l"(a), "l"(b)); return c;
}
__device__ __forceinline__ u64 fma2(u64 a, u64 b, u64 c) {
    u64 d; asm("fma.rn.f32x2 %0, %1, %2, %3;" : "=l"(d) : "l"(a), "l"(b), "l"(c)); return d;
}
__device__ __forceinline__ float ex2(float x) {
    float y; asm("ex2.approx.ftz.f32 %0, %1;" : "=f"(y) : "f"(x)); return y;
}
__device__ __forceinline__ float lg2(float x) {
    float y; asm("lg2.approx.f32 %0, %1;" : "=f"(y) : "f"(x)); return y;
}
// ---- L2-direct loads (bypass possibly-stale L1; no ordering side-effects) ----
__device__ __forceinline__ int ldcg(const int* p) {
    int v; asm volatile("ld.global.cg.b32 %0, [%1];" : "=r"(v) : "l"(p)); return v;
}
__device__ __forceinline__ u64 ldcg64(const u64* p) {
    u64 v; asm volatile("ld.global.cg.b64 %0, [%1];" : "=l"(v) : "l"(p)); return v;
}
__device__ __forceinline__ float ldcgf(const float* p) {
    float v; asm volatile("ld.global.cg.f32 %0, [%1];" : "=f"(v) : "l"(p)); return v;
}

// ---------------------------------------------------------------------------
__device__ __forceinline__ float get_scale(int slot) {
    int v = ldcg(&g_max[slot][0]);
    #pragma unroll
    for (int k = 1; k < 8; k++) v = max(v, ldcg(&g_max[slot][k]));
    float m = __int_as_float(v);
    return (m > 1.0f) ? __fdividef(1.0f, m) : 1.0f;
}

__device__ __forceinline__ void block_max_atomic(float val, int slot) {
    int v = __float_as_int(val);   // valid ordering: all values non-negative
    #pragma unroll
    for (int o = 16; o > 0; o >>= 1) v = max(v, __shfl_xor_sync(0xffffffffu, v, o));
    __shared__ int s_red[8];
    if ((threadIdx.x & 31) == 0) s_red[threadIdx.x >> 5] = v;
    __syncthreads();
    if (threadIdx.x == 0) {
        int m = s_red[0];
        #pragma unroll
        for (int k = 1; k < 8; k++) m = max(m, s_red[k]);
        atomicMax(&g_max[slot][blockIdx.x & 7], m);
    }
}

// Flush-free, acquire-free grid barrier.
//  - arrive: atom.release.gpu (orders producer stores; write-through L1 -> cheap)
//  - spin:   ld.relaxed.gpu   (L2-direct poll, NO invalidation per iteration)
// Consumers need no acquire: rotated buffers are never L1-stale; all other
// cross-phase data is read via ld.cg (L2-direct).
__device__ __forceinline__ void gsync() {
    __syncthreads();
    if (threadIdx.x == 0) {
        unsigned gen;
        asm volatile("ld.relaxed.gpu.global.b32 %0, [%1];" : "=r"(gen) : "l"(&g_gen));
        unsigned old;
        asm volatile("atom.release.gpu.global.add.u32 %0, [%1], 1;"
                     : "=r"(old) : "l"(&g_cnt) : "memory");
        if (old == NBLK - 1) {
            asm volatile("st.relaxed.gpu.global.b32 [%0], 0;" :: "l"(&g_cnt) : "memory");
            asm volatile("st.release.gpu.global.b32 [%0], %1;"
                         :: "l"(&g_gen), "r"(gen + 1) : "memory");
        } else {
            unsigned cur;
            do {
                asm volatile("ld.relaxed.gpu.global.b32 %0, [%1];" : "=r"(cur) : "l"(&g_gen));
            } while (cur == gen);
        }
    }
    __syncthreads();
}

// ---------------------------------------------------------------------------
__global__ void __launch_bounds__(NTHR, 4)
k_persist(const float* __restrict__ x, const float* __restrict__ W,
          const int* __restrict__ I, float* __restrict__ out) {
    const int tid  = threadIdx.x;
    const int lane = tid & 31;
    const int hf   = lane >> 4;                   // item-of-pair selector
    const int j    = lane & 15;                   // b-pair index
    const int wid  = blockIdx.x * 8 + (tid >> 5); // 0..NW-1
    const int gtid = blockIdx.x * NTHR + tid;

    // Phase B/merge ownership: spread over ALL blocks (every 4th warp busy)
    const bool bOwn = ((wid & 3) == 0) && ((wid >> 2) < NG / 2);
    const int  g    = 2 * (wid >> 2) + hf;        // valid when bOwn

    // ---- init: pack x -> g_R[0], Ws = softmax(W), reset max banks ----
    {
        if (gtid < NG * 16) {                     // gtid = jj*NG + gg
            int jj = gtid >> 11, gg = gtid & (NG - 1);
            g_R[0][gg * 16 + jj] = pk(x[(2 * jj) * NG + gg], x[(2 * jj + 1) * NG + gg]);
        }
        if (blockIdx.x == 0 && tid < NM) {
            float mx = -1e30f;
            #pragma unroll
            for (int c = 0; c < NC; c++) mx = fmaxf(mx, W[tid * NC + c]);
            float e[NC]; float sum = 0.0f;
            #pragma unroll
            for (int c = 0; c < NC; c++) { e[c] = ex2((W[tid * NC + c] - mx) * 1.4426950409f); sum += e[c]; }
            float inv = __fdividef(1.0f, sum);
            #pragma unroll
            for (int c = 0; c < NC; c++) g_Ws[tid * NC + c] = e[c] * inv;
        }
        if (blockIdx.x == 1 && tid < 128)
            ((int*)g_max)[tid] = (tid >= 15 * 8) ? __float_as_int(1.0f) : 0;
    }
    gsync();

    __shared__ u64 ws2[NM * NC];                  // broadcast-packed softmax(W)
    { float w = ldcgf(&g_Ws[tid]); ws2[tid] = pk(w, w); }
    __syncthreads();

    int slotR = 15;   // iteration 0 uses x unscaled (slot 15 == 1.0)

    #pragma unroll 1
    for (int it = 0; it < 5; it++) {
        const int slotCv = 3 * it, slotHs = 3 * it + 1, slotRn = 3 * it + 2;
        const u64* Rin  = g_R[it];
        u64*       Rout = g_R[it + 1];

        // ---- Phase A: pair of (c,g) items per warp; f32x2; L1-cached gathers ----
        {
            float sR = get_scale(slotR);
            float s3 = sR * sR * sR;
            float kexp = s3 * KEXP;               // scale folded into LSE constant
            u64  kexp2 = pk(kexp, kexp);
            float lmax = 0.0f;
            int p0 = (int)(((long long)wid * NPAIR) / NW);
            int p1 = (int)(((long long)(wid + 1) * NPAIR) / NW);
            #pragma unroll 1
            for (int P = p0; P < p1; P++) {
                int item = 2 * P + hf;
                const int4* ip = reinterpret_cast<const int4*>(I) + item * 6;
                int4 a0 = ip[0], a1 = ip[1], a2 = ip[2],
                     a3 = ip[3], a4 = ip[4], a5 = ip[5];
                #define GA(i) Rin[(i) * 16 + j]
                u64 b0 = mul2(mul2(GA(a0.x), GA(a0.y)), GA(a0.z));
                u64 b1 = mul2(mul2(GA(a0.w), GA(a1.x)), GA(a1.y));
                u64 b2 = mul2(mul2(GA(a1.z), GA(a1.w)), GA(a2.x));
                u64 b3 = mul2(mul2(GA(a2.y), GA(a2.z)), GA(a2.w));
                u64 b4 = mul2(mul2(GA(a3.x), GA(a3.y)), GA(a3.z));
                u64 b5 = mul2(mul2(GA(a3.w), GA(a4.x)), GA(a4.y));
                u64 b6 = mul2(mul2(GA(a4.z), GA(a4.w)), GA(a5.x));
                u64 b7 = mul2(mul2(GA(a5.y), GA(a5.z)), GA(a5.w));
                #undef GA
                float2 c0 = unpk(b0), c1 = unpk(b1), c2 = unpk(b2), c3 = unpk(b3);
                float2 c4 = unpk(b4), c5 = unpk(b5), c6 = unpk(b6), c7 = unpk(b7);
                float mxx = fmaxf(fmaxf(fmaxf(c0.x, c1.x), fmaxf(c2.x, c3.x)),
                                  fmaxf(fmaxf(c4.x, c5.x), fmaxf(c6.x, c7.x)));
                float mxy = fmaxf(fmaxf(fmaxf(c0.y, c1.y), fmaxf(c2.y, c3.y)),
                                  fmaxf(fmaxf(c4.y, c5.y), fmaxf(c6.y, c7.y)));
                u64 mneg = pk(-mxx * kexp, -mxy * kexp);
                float sx = 0.0f, sy = 0.0f;
                {
                    u64 t0 = fma2(b0, kexp2, mneg); float2 f0 = unpk(t0); sx += ex2(f0.x); sy += ex2(f0.y);
                    u64 t1 = fma2(b1, kexp2, mneg); float2 f1 = unpk(t1); sx += ex2(f1.x); sy += ex2(f1.y);
                    u64 t2 = fma2(b2, kexp2, mneg); float2 f2 = unpk(t2); sx += ex2(f2.x); sy += ex2(f2.y);
                    u64 t3 = fma2(b3, kexp2, mneg); float2 f3 = unpk(t3); sx += ex2(f3.x); sy += ex2(f3.y);
                    u64 t4 = fma2(b4, kexp2, mneg); float2 f4 = unpk(t4); sx += ex2(f4.x); sy += ex2(f4.y);
                    u64 t5 = fma2(b5, kexp2, mneg); float2 f5 = unpk(t5); sx += ex2(f5.x); sy += ex2(f5.y);
                    u64 t6 = fma2(b6, kexp2, mneg); float2 f6 = unpk(t6); sx += ex2(f6.x); sy += ex2(f6.y);
                    u64 t7 = fma2(b7, kexp2, mneg); float2 f7 = unpk(t7); sx += ex2(f7.x); sy += ex2(f7.y);
                }
                float cvx = fmaf(lg2(sx), KLOG, mxx * s3);
                float cvy = fmaf(lg2(sy), KLOG, mxy * s3);
                g_Cv2[item * 16 + j] = pk(cvx, cvy);
                lmax = fmaxf(lmax, fmaxf(cvx, cvy));
            }
            block_max_atomic(lmax, slotCv);
        }
        gsync();

        // ---- Phase B: matvec + LSE_m; Cv via ld.cg; hs held in registers ----
        float hsx = 0.0f, hsy = 0.0f;
        {
            float s1 = get_scale(slotCv);
            float lmax = 0.0f;
            if (bOwn) {
                u64 h[NM];
                #pragma unroll
                for (int m = 0; m < NM; m++) h[m] = 0ull;
                #pragma unroll
                for (int c = 0; c < NC; c++) {
                    u64 cvc = ldcg64(&g_Cv2[(c * NG + g) * 16 + j]);
                    #pragma unroll
                    for (int m = 0; m < NM; m++) h[m] = fma2(ws2[m * NC + c], cvc, h[m]);
                }
                float2 hh[NM];
                #pragma unroll
                for (int m = 0; m < NM; m++) hh[m] = unpk(h[m]);
                float mxx = hh[0].x, mxy = hh[0].y;
                #pragma unroll
                for (int m = 1; m < NM; m++) { mxx = fmaxf(mxx, hh[m].x); mxy = fmaxf(mxy, hh[m].y); }
                float k1 = s1 * KEXP;
                u64 k12 = pk(k1, k1), mneg = pk(-mxx * k1, -mxy * k1);
                float sx = 0.0f, sy = 0.0f;
                #pragma unroll
                for (int m = 0; m < NM; m++) {
                    u64 t = fma2(h[m], k12, mneg);
                    float2 f = unpk(t);
                    sx += ex2(f.x); sy += ex2(f.y);
                }
                hsx = fmaf(lg2(sx), KLOG, mxx * s1);
                hsy = fmaf(lg2(sy), KLOG, mxy * s1);
                lmax = fmaxf(hsx, hsy);
            }
            block_max_atomic(lmax, slotHs);
        }
        gsync();

        // ---- merge: same warps, hs from registers; write next R buffer ----
        {
            float sR = get_scale(slotR);
            float s2 = get_scale(slotHs);
            float lmax = 0.0f;
            if (bOwn) {
                float2 rr = unpk(Rin[g * 16 + j]);
                float ax = rr.x * sR, ay = rr.y * sR;
                float bx = hsx * s2,  by = hsy * s2;
                float mxx = fmaxf(ax, bx), mnx = fminf(ax, bx);
                float mxy = fmaxf(ay, by), mny = fminf(ay, by);
                float rx = fmaf(lg2(1.0f + ex2((mnx - mxx) * KEXP)), KLOG, mxx);
                float ry = fmaf(lg2(1.0f + ex2((mny - mxy) * KEXP)), KLOG, mxy);
                Rout[g * 16 + j] = pk(rx, ry);
                lmax = fmaxf(rx, ry);
            }
            block_max_atomic(lmax, slotRn);
        }
        gsync();

        slotR = slotRn;
    }

    // ---- output: scale + unpack back to (B, G); g_R[5] never read before ----
    if (gtid < NG * 32) {                         // gtid = b*NG + gg
        float s = get_scale(slotR);
        int b = gtid >> 11, gg = gtid & (NG - 1);
        float2 v = unpk(g_R[5][gg * 16 + (b >> 1)]);
        out[gtid] = ((b & 1) ? v.y : v.x) * s;
    }
}

// ---------------------------------------------------------------------------
extern "C" void kernel_launch(void* const* d_in, const int* in_sizes, int n_in,
                              void* d_out, int out_size) {
    const float* x = (const float*)d_in[0];   // (32, 2048) f32
    const float* W = (const float*)d_in[1];   // (16, 16) f32
    const int*   I = (const int*)  d_in[2];   // (16, 2048, 8, 3) i32
    float* out = (float*)d_out;               // (32, 2048) f32

    k_persist<<<NBLK, NTHR>>>(x, W, I, out);
}

// round 9
// speedup vs baseline: 3.4229x; 3.2520x over previous
#include <cuda_runtime.h>

// Problem constants
#define NG 2048   // G
#define NC 16     // C
#define NM 16     // m
// exp(x/gamma) = ex2(x * 100 * log2(e));  gamma*ln(s) = lg2(s) * gamma*ln2
#define KEXP 144.2695040889f
#define KLOG 0.00693147180560f
#define NPAIR (NC * NG / 2)      // 16384 (c,g) item-pairs in kA

typedef unsigned long long u64;

// Packed layouts: element [g*16 + j] = (val[b=2j], val[b=2j+1])
__device__ u64   g_Rt2[NG * 16];         // R (un-normalized; scale in g_max)
__device__ u64   g_Cv2[NC * NG * 16];    // Cv_pre
__device__ u64   g_Hs2[NG * 16];         // Hs_pre
__device__ float g_Ws[NM * NC];          // softmax(W)
__device__ int   g_max[16][8];           // banked float-bit maxes (values >= 0)
// slot 3i=Cv max, 3i+1=Hs max, 3i+2=R max (iter i); slot 15 = constant 1.0

// ---- f32x2 helpers (sm_103a packed fp32) ----
__device__ __forceinline__ u64 pk(float x, float y) {
    u64 v; asm("mov.b64 %0, {%1,%2};" : "=l"(v) : "f"(x), "f"(y)); return v;
}
__device__ __forceinline__ float2 unpk(u64 v) {
    float2 r; asm("mov.b64 {%0,%1}, %2;" : "=f"(r.x), "=f"(r.y) : "l"(v)); return r;
}
__device__ __forceinline__ u64 mul2(u64 a, u64 b) {
    u64 c; asm("mul.rn.f32x2 %0, %1, %2;" : "=l"(c) : "l"(a), "l"(b)); return c;
}
__device__ __forceinline__ u64 fma2(u64 a, u64 b, u64 c) {
    u64 d; asm("fma.rn.f32x2 %0, %1, %2, %3;" : "=l"(d) : "l"(a), "l"(b), "l"(c)); return d;
}
__device__ __forceinline__ float ex2(float x) {
    float y; asm("ex2.approx.ftz.f32 %0, %1;" : "=f"(y) : "f"(x)); return y;
}
__device__ __forceinline__ float lg2(float x) {
    float y; asm("lg2.approx.f32 %0, %1;" : "=f"(y) : "f"(x)); return y;
}

// ---------------------------------------------------------------------------
__device__ __forceinline__ float get_scale(int slot) {
    int v = g_max[slot][0];
    #pragma unroll
    for (int k = 1; k < 8; k++) v = max(v, g_max[slot][k]);
    float m = __int_as_float(v);
    return (m > 1.0f) ? __fdividef(1.0f, m) : 1.0f;
}

// warp->block max reduce, one atomicMax per block. All 256 threads must call.
__device__ __forceinline__ void block_max_atomic(float val, int slot) {
    int v = __float_as_int(val);   // valid ordering: all values non-negative
    #pragma unroll
    for (int o = 16; o > 0; o >>= 1) v = max(v, __shfl_xor_sync(0xffffffffu, v, o));
    __shared__ int s_red[8];
    if ((threadIdx.x & 31) == 0) s_red[threadIdx.x >> 5] = v;
    __syncthreads();
    if (threadIdx.x == 0) {
        int m = s_red[0];
        #pragma unroll
        for (int k = 1; k < 8; k++) m = max(m, s_red[k]);
        atomicMax(&g_max[slot][blockIdx.x & 7], m);
    }
}

// ---------------------------------------------------------------------------
// init: pack x -> Rt2, Ws = softmax(W), reset max banks.  grid 128 x 256
__global__ void k_init(const float* __restrict__ x, const float* __restrict__ W) {
    int t = blockIdx.x * blockDim.x + threadIdx.x;   // t = jj*NG + g
    int jj = t >> 11, g = t & (NG - 1);
    g_Rt2[g * 16 + jj] = pk(x[(2 * jj) * NG + g], x[(2 * jj + 1) * NG + g]);

    if (blockIdx.x == 0) {
        if (threadIdx.x < NM) {
            int m = threadIdx.x;
            float mx = -1e30f;
            #pragma unroll
            for (int c = 0; c < NC; c++) mx = fmaxf(mx, W[m * NC + c]);
            float e[NC]; float sum = 0.0f;
            #pragma unroll
            for (int c = 0; c < NC; c++) { e[c] = ex2((W[m * NC + c] - mx) * 1.4426950409f); sum += e[c]; }
            float inv = __fdividef(1.0f, sum);
            #pragma unroll
            for (int c = 0; c < NC; c++) g_Ws[m * NC + c] = e[c] * inv;
        }
        if (threadIdx.x >= 64 && threadIdx.x < 192) {
            int k = threadIdx.x - 64;
            ((int*)g_max)[k] = (k >= 15 * 8) ? __float_as_int(1.0f) : 0;  // slot 15 == 1.0
        }
    }
}

// ---------------------------------------------------------------------------
// kA: one (c,g)-item pair per warp (half-warp each), f32x2 throughout.
// grid 2048 x 256 (16384 warps == NPAIR)
__global__ void __launch_bounds__(256, 4)
kA(const int* __restrict__ I, int slotR, int slotOut) {
    const int tid  = threadIdx.x;
    const int lane = tid & 31;
    const int hf   = lane >> 4;                   // item-of-pair selector
    const int j    = lane & 15;                   // b-pair index
    const int P    = blockIdx.x * 8 + (tid >> 5); // pair id

    float sR = get_scale(slotR);
    float s3 = sR * sR * sR;
    float kexp = s3 * KEXP;                       // scale folded into LSE constant
    u64  kexp2 = pk(kexp, kexp);

    int item = 2 * P + hf;
    const int4* ip = reinterpret_cast<const int4*>(I) + item * 6;
    int4 a0 = ip[0], a1 = ip[1], a2 = ip[2], a3 = ip[3], a4 = ip[4], a5 = ip[5];
    #define GA(i) g_Rt2[(i) * 16 + j]
    u64 b0 = mul2(mul2(GA(a0.x), GA(a0.y)), GA(a0.z));
    u64 b1 = mul2(mul2(GA(a0.w), GA(a1.x)), GA(a1.y));
    u64 b2 = mul2(mul2(GA(a1.z), GA(a1.w)), GA(a2.x));
    u64 b3 = mul2(mul2(GA(a2.y), GA(a2.z)), GA(a2.w));
    u64 b4 = mul2(mul2(GA(a3.x), GA(a3.y)), GA(a3.z));
    u64 b5 = mul2(mul2(GA(a3.w), GA(a4.x)), GA(a4.y));
    u64 b6 = mul2(mul2(GA(a4.z), GA(a4.w)), GA(a5.x));
    u64 b7 = mul2(mul2(GA(a5.y), GA(a5.z)), GA(a5.w));
    #undef GA
    float2 c0 = unpk(b0), c1 = unpk(b1), c2 = unpk(b2), c3 = unpk(b3);
    float2 c4 = unpk(b4), c5 = unpk(b5), c6 = unpk(b6), c7 = unpk(b7);
    float mxx = fmaxf(fmaxf(fmaxf(c0.x, c1.x), fmaxf(c2.x, c3.x)),
                      fmaxf(fmaxf(c4.x, c5.x), fmaxf(c6.x, c7.x)));
    float mxy = fmaxf(fmaxf(fmaxf(c0.y, c1.y), fmaxf(c2.y, c3.y)),
                      fmaxf(fmaxf(c4.y, c5.y), fmaxf(c6.y, c7.y)));
    u64 mneg = pk(-mxx * kexp, -mxy * kexp);
    float sx = 0.0f, sy = 0.0f;
    {
        u64 t0 = fma2(b0, kexp2, mneg); float2 f0 = unpk(t0); sx += ex2(f0.x); sy += ex2(f0.y);
        u64 t1 = fma2(b1, kexp2, mneg); float2 f1 = unpk(t1); sx += ex2(f1.x); sy += ex2(f1.y);
        u64 t2 = fma2(b2, kexp2, mneg); float2 f2 = unpk(t2); sx += ex2(f2.x); sy += ex2(f2.y);
        u64 t3 = fma2(b3, kexp2, mneg); float2 f3 = unpk(t3); sx += ex2(f3.x); sy += ex2(f3.y);
        u64 t4 = fma2(b4, kexp2, mneg); float2 f4 = unpk(t4); sx += ex2(f4.x); sy += ex2(f4.y);
        u64 t5 = fma2(b5, kexp2, mneg); float2 f5 = unpk(t5); sx += ex2(f5.x); sy += ex2(f5.y);
        u64 t6 = fma2(b6, kexp2, mneg); float2 f6 = unpk(t6); sx += ex2(f6.x); sy += ex2(f6.y);
        u64 t7 = fma2(b7, kexp2, mneg); float2 f7 = unpk(t7); sx += ex2(f7.x); sy += ex2(f7.y);
    }
    float cvx = fmaf(lg2(sx), KLOG, mxx * s3);
    float cvy = fmaf(lg2(sy), KLOG, mxy * s3);
    g_Cv2[item * 16 + j] = pk(cvx, cvy);
    block_max_atomic(fmaxf(cvx, cvy), slotOut);
}

// ---------------------------------------------------------------------------
// kB: one g-pair per warp; matvec over c + LSE over m, f32x2.
// grid 128 x 256 (1024 warps == NG/2)
__global__ void __launch_bounds__(256, 4)
kB(int slotCv, int slotOut) {
    __shared__ u64 ws2[NM * NC];
    { float w = g_Ws[threadIdx.x]; ws2[threadIdx.x] = pk(w, w); }
    __syncthreads();

    const int tid  = threadIdx.x;
    const int lane = tid & 31;
    const int hf   = lane >> 4;
    const int j    = lane & 15;
    const int g    = 2 * (blockIdx.x * 8 + (tid >> 5)) + hf;

    float s1 = get_scale(slotCv);

    u64 h[NM];
    #pragma unroll
    for (int m = 0; m < NM; m++) h[m] = 0ull;
    #pragma unroll
    for (int c = 0; c < NC; c++) {
        u64 cvc = g_Cv2[(c * NG + g) * 16 + j];
        #pragma unroll
        for (int m = 0; m < NM; m++) h[m] = fma2(ws2[m * NC + c], cvc, h[m]);
    }
    float2 hh[NM];
    #pragma unroll
    for (int m = 0; m < NM; m++) hh[m] = unpk(h[m]);
    float mxx = hh[0].x, mxy = hh[0].y;
    #pragma unroll
    for (int m = 1; m < NM; m++) { mxx = fmaxf(mxx, hh[m].x); mxy = fmaxf(mxy, hh[m].y); }
    float k1 = s1 * KEXP;                         // scale folded into LSE
    u64 k12 = pk(k1, k1), mneg = pk(-mxx * k1, -mxy * k1);
    float sx = 0.0f, sy = 0.0f;
    #pragma unroll
    for (int m = 0; m < NM; m++) {
        u64 t = fma2(h[m], k12, mneg);
        float2 f = unpk(t);
        sx += ex2(f.x); sy += ex2(f.y);
    }
    float hsx = fmaf(lg2(sx), KLOG, mxx * s1);
    float hsy = fmaf(lg2(sy), KLOG, mxy * s1);
    g_Hs2[g * 16 + j] = pk(hsx, hsy);
    block_max_atomic(fmaxf(hsx, hsy), slotOut);
}

// ---------------------------------------------------------------------------
// kC: elementwise 2-way softor merge (both b-halves per thread), R in place.
// grid 128 x 256 (32768 threads == NG*16)
__global__ void __launch_bounds__(256, 4)
kC(int slotR, int slotHs, int slotOut) {
    int t = blockIdx.x * blockDim.x + threadIdx.x;
    float sR = get_scale(slotR);
    float s2 = get_scale(slotHs);

    float2 rr = unpk(g_Rt2[t]);
    float2 hv = unpk(g_Hs2[t]);
    float ax = rr.x * sR, ay = rr.y * sR;
    float bx = hv.x * s2, by = hv.y * s2;
    float mxx = fmaxf(ax, bx), mnx = fminf(ax, bx);
    float mxy = fmaxf(ay, by), mny = fminf(ay, by);
    float rx = fmaf(lg2(1.0f + ex2((mnx - mxx) * KEXP)), KLOG, mxx);
    float ry = fmaf(lg2(1.0f + ex2((mny - mxy) * KEXP)), KLOG, mxy);
    g_Rt2[t] = pk(rx, ry);
    block_max_atomic(fmaxf(rx, ry), slotOut);
}

// ---------------------------------------------------------------------------
// output: scale + unpack back to (B, G); coalesced stores.  grid 256 x 256
__global__ void k_out(float* __restrict__ out, int slotR) {
    int t = blockIdx.x * blockDim.x + threadIdx.x;   // t = b*NG + g
    float s = get_scale(slotR);
    int b = t >> 11, g = t & (NG - 1);
    float2 v = unpk(g_Rt2[g * 16 + (b >> 1)]);
    out[t] = ((b & 1) ? v.y : v.x) * s;
}

// ---------------------------------------------------------------------------
extern "C" void kernel_launch(void* const* d_in, const int* in_sizes, int n_in,
                              void* d_out, int out_size) {
    const float* x = (const float*)d_in[0];   // (32, 2048) f32
    const float* W = (const float*)d_in[1];   // (16, 16) f32
    const int*   I = (const int*)  d_in[2];   // (16, 2048, 8, 3) i32
    float* out = (float*)d_out;               // (32, 2048) f32

    k_init<<<128, 256>>>(x, W);

    int slotR = 15;  // constant 1.0 (x used unscaled in iteration 0)
    for (int i = 0; i < 5; i++) {
        kA<<<2048, 256>>>(I, slotR, 3 * i);
        kB<<<128,  256>>>(3 * i, 3 * i + 1);
        kC<<<128,  256>>>(slotR, 3 * i + 1, 3 * i + 2);
        slotR = 3 * i + 2;
    }

    k_out<<<256, 256>>>(out, slotR);
}